// round 2
// baseline (speedup 1.0000x reference)
#include <cuda_runtime.h>
#include <math.h>

// ---------------- problem dims ----------------
#define BB   32
#define CC   8
#define TT   20000
#define PP   25
#define LL   800        // TT/PP, no padding needed
#define CP   200        // CC*PP
#define DD   512
#define HH   8
#define DHH  64
#define MM   256
#define NLAYER 2
#define FFND 1024
#define NC   10
#define HID  128
#define ROWS (BB*LL)    // 25600

// ---------------- scratch arena (device global; no allocation allowed) ---
// Layout (floats):
//   h    : ROWS*DD                      (persistent residual stream)
//   a    : ROWS*DD                      (LN output / GEMM input)
//   big  : ROWS*FFND                    (ffn hidden; aliases q|k|v: 3*ROWS*DD = ROWS*FFND*1.5 -> need max)
//   qf   : BB*HH*LL*MM
//   kf   : BB*HH*LL*MM
//   att  : ROWS*DD                      (also aliases tok: tok is ROWS*CP < ROWS*DD)
//   kv   : BB*HH*MM*DHH
//   ksum : BB*HH*MM
//   misc : scr + alp + feat
#define SZ_H    (ROWS*DD)
#define SZ_BIG  (3*ROWS*DD)            // holds q,k,v concurrently OR ffn hidden (ROWS*FFND = 2*ROWS*DD <= 3*ROWS*DD)
#define SZ_PHI  (BB*HH*LL*MM)
#define OFF_H    0
#define OFF_A    (OFF_H   + SZ_H)
#define OFF_BIG  (OFF_A   + SZ_H)
#define OFF_QF   (OFF_BIG + SZ_BIG)
#define OFF_KF   (OFF_QF  + SZ_PHI)
#define OFF_ATT  (OFF_KF  + SZ_PHI)    // also tok (ROWS*CP < ROWS*DD)
#define OFF_KV   (OFF_ATT + SZ_H)
#define OFF_KSUM (OFF_KV  + BB*HH*MM*DHH)
#define OFF_SCR  (OFF_KSUM+ BB*HH*MM)
#define OFF_ALP  (OFF_SCR + ROWS)
#define OFF_FEAT (OFF_ALP + ROWS)
#define ARENA_SZ (OFF_FEAT + BB*2*DD)

__device__ float g_arena[ARENA_SZ];

// ---------------- patchify: x(B,C,T) -> tok(B,L,C*P) ----------------
__global__ void patchify_kernel(const float* __restrict__ x, float* __restrict__ tok) {
    int bl = blockIdx.x;
    int b = bl / LL, l = bl % LL;
    int t = threadIdx.x;              // 200 threads
    int c = t / PP, p = t % PP;
    tok[bl * CP + t] = x[(b * CC + c) * TT + l * PP + p];
}

// ---------------- generic tiled GEMM: C = act(A@W + bias) [+ C] -----------
// A: (Mr x K) row-major, W: (K x N) row-major, C: (Mr x N) row-major.
// ACT: 0 none, 1 exact gelu, 2 tanh.  RESID: C += result.
template<int ACT, bool RESID>
__global__ void __launch_bounds__(256, 2)
gemm_kernel(const float* __restrict__ A, const float* __restrict__ W,
            const float* __restrict__ bias, float* __restrict__ C,
            int Mr, int N, int K)
{
    __shared__ float As[8][128];   // transposed A tile: As[k][m]
    __shared__ float Bs[8][128];   // Bs[k][n]
    int tid = threadIdx.x;
    int m0 = blockIdx.y * 128, n0 = blockIdx.x * 128;
    int tx = tid % 16, ty = tid / 16;

    float acc[8][8];
#pragma unroll
    for (int i = 0; i < 8; i++)
#pragma unroll
        for (int j = 0; j < 8; j++) acc[i][j] = 0.f;

    int arow = tid >> 1, acol = (tid & 1) * 4;          // A tile: 128x8
    int brow = tid >> 5, bcol = (tid & 31) * 4;         // B tile: 8x128
    const float* Aptr = A + (long)(m0 + arow) * K + acol;
    const float* Wptr = W + (long)brow * N + n0 + bcol;

    for (int k0 = 0; k0 < K; k0 += 8) {
        float4 av = *(const float4*)(Aptr + k0);
        As[acol + 0][arow] = av.x;
        As[acol + 1][arow] = av.y;
        As[acol + 2][arow] = av.z;
        As[acol + 3][arow] = av.w;
        *(float4*)&Bs[brow][bcol] = *(const float4*)(Wptr + (long)k0 * N);
        __syncthreads();
#pragma unroll
        for (int k = 0; k < 8; k++) {
            float4 a0 = *(float4*)&As[k][ty * 8];
            float4 a1 = *(float4*)&As[k][ty * 8 + 4];
            float4 b0 = *(float4*)&Bs[k][tx * 8];
            float4 b1 = *(float4*)&Bs[k][tx * 8 + 4];
            float ar[8] = {a0.x, a0.y, a0.z, a0.w, a1.x, a1.y, a1.z, a1.w};
            float br[8] = {b0.x, b0.y, b0.z, b0.w, b1.x, b1.y, b1.z, b1.w};
#pragma unroll
            for (int i = 0; i < 8; i++)
#pragma unroll
                for (int j = 0; j < 8; j++) acc[i][j] += ar[i] * br[j];
        }
        __syncthreads();
    }

#pragma unroll
    for (int i = 0; i < 8; i++) {
        int row = m0 + ty * 8 + i;
#pragma unroll
        for (int j = 0; j < 8; j++) {
            int col = n0 + tx * 8 + j;
            float v = acc[i][j];
            if (bias) v += bias[col];
            if (ACT == 1) v = 0.5f * v * (1.0f + erff(v * 0.70710678118654752f));
            if (ACT == 2) v = tanhf(v);
            float* cp = &C[(long)row * N + col];
            if (RESID) v += *cp;
            *cp = v;
        }
    }
}

// ---------------- LayerNorm over D=512 -------------------------------
__global__ void ln_kernel(const float* __restrict__ X, const float* __restrict__ g,
                          const float* __restrict__ bta, float* __restrict__ Y)
{
    long row = blockIdx.x;
    int tid = threadIdx.x;  // 256
    __shared__ float sh[8];
    float v0 = X[row * DD + tid];
    float v1 = X[row * DD + tid + 256];
    float s = v0 + v1;
#pragma unroll
    for (int o = 16; o > 0; o >>= 1) s += __shfl_xor_sync(0xffffffffu, s, o);
    if ((tid & 31) == 0) sh[tid >> 5] = s;
    __syncthreads();
    if (tid == 0) { float t = 0; for (int i = 0; i < 8; i++) t += sh[i]; sh[0] = t; }
    __syncthreads();
    float mu = sh[0] * (1.0f / DD);
    __syncthreads();
    float d0 = v0 - mu, d1 = v1 - mu;
    s = d0 * d0 + d1 * d1;
#pragma unroll
    for (int o = 16; o > 0; o >>= 1) s += __shfl_xor_sync(0xffffffffu, s, o);
    if ((tid & 31) == 0) sh[tid >> 5] = s;
    __syncthreads();
    if (tid == 0) { float t = 0; for (int i = 0; i < 8; i++) t += sh[i]; sh[0] = t; }
    __syncthreads();
    float var = sh[0] * (1.0f / DD);
    float rstd = rsqrtf(var + 1e-5f);
    Y[row * DD + tid]       = d0 * rstd * g[tid]       + bta[tid];
    Y[row * DD + tid + 256] = d1 * rstd * g[tid + 256] + bta[tid + 256];
}

// ---------------- FAVOR+ phi: (B,L,D) -> (B,H,L,M), Q and K in one launch -
__global__ void phi_kernel(const float* __restrict__ Q, const float* __restrict__ K,
                           const float* __restrict__ omega,
                           float* __restrict__ QPhi, float* __restrict__ KPhi)
{
    int bl = blockIdx.x;
    const float* X = (bl < ROWS) ? Q : K;
    float* Phi = (bl < ROWS) ? QPhi : KPhi;
    if (bl >= ROWS) bl -= ROWS;
    __shared__ float xs[DD];
    int tid = threadIdx.x;  // 256
    const float inv4 = 0.35355339059327379f;  // 1/64^0.25
    xs[tid]       = X[(long)bl * DD + tid]       * inv4;
    xs[tid + 256] = X[(long)bl * DD + tid + 256] * inv4;
    __syncthreads();
    int h = tid >> 5, lane = tid & 31;
    const float* xh = &xs[h * DHH];
    float nsq = 0.f;
#pragma unroll
    for (int d = 0; d < DHH; d++) nsq += xh[d] * xh[d];
    nsq *= 0.5f;
    float acc[8];
#pragma unroll
    for (int j = 0; j < 8; j++) acc[j] = 0.f;
    for (int d = 0; d < DHH; d++) {
        float xv = xh[d];
        const float* om = omega + d * MM + lane;
#pragma unroll
        for (int j = 0; j < 8; j++) acc[j] += xv * om[j * 32];
    }
    int b = bl / LL, l = bl % LL;
    float* outp = Phi + ((long)(b * HH + h) * LL + l) * MM + lane;
#pragma unroll
    for (int j = 0; j < 8; j++) outp[j * 32] = expf(acc[j] - nsq) * 0.0625f;
}

// ---------------- Ksum[b,h,m] = sum_l Kf ----------------------------
__global__ void ksum_kernel(const float* __restrict__ Kf, float* __restrict__ Ksum) {
    int bh = blockIdx.x;
    int m = threadIdx.x;   // 256
    const float* p = Kf + (long)bh * LL * MM + m;
    float s = 0.f;
    for (int l = 0; l < LL; l++) s += p[l * MM];
    Ksum[bh * MM + m] = s;
}

// ---------------- KV[b,h,m,d] = sum_l Kf[l,m] V[l,d] ----------------
__global__ void __launch_bounds__(256)
kv_kernel(const float* __restrict__ Kf, const float* __restrict__ V,
          float* __restrict__ KV)
{
    int bh = blockIdx.x >> 1, mh = blockIdx.x & 1;
    int b = bh / HH, h = bh % HH;
    __shared__ float Ks[32][128];
    __shared__ float Vs[32][64];
    int tid = threadIdx.x;
    int tm = tid >> 3, td = tid & 7;
    float acc[4][8];
#pragma unroll
    for (int i = 0; i < 4; i++)
#pragma unroll
        for (int j = 0; j < 8; j++) acc[i][j] = 0.f;

    for (int l0 = 0; l0 < LL; l0 += 32) {
#pragma unroll
        for (int r = 0; r < 4; r++) {
            int idx = tid * 4 + r * 1024;
            int lr = idx >> 7, mc = idx & 127;
            *(float4*)&Ks[lr][mc] =
                *(const float4*)&Kf[((long)bh * LL + l0 + lr) * MM + mh * 128 + mc];
        }
#pragma unroll
        for (int r = 0; r < 2; r++) {
            int idx = tid * 4 + r * 1024;
            int lr = idx >> 6, dc = idx & 63;
            *(float4*)&Vs[lr][dc] =
                *(const float4*)&V[((long)b * LL + l0 + lr) * DD + h * 64 + dc];
        }
        __syncthreads();
#pragma unroll 4
        for (int l = 0; l < 32; l++) {
            float km[4];
#pragma unroll
            for (int i = 0; i < 4; i++) km[i] = Ks[l][tm * 4 + i];
            float4 v0 = *(float4*)&Vs[l][td * 8];
            float4 v1 = *(float4*)&Vs[l][td * 8 + 4];
            float vr[8] = {v0.x, v0.y, v0.z, v0.w, v1.x, v1.y, v1.z, v1.w};
#pragma unroll
            for (int i = 0; i < 4; i++)
#pragma unroll
                for (int j = 0; j < 8; j++) acc[i][j] += km[i] * vr[j];
        }
        __syncthreads();
    }
#pragma unroll
    for (int i = 0; i < 4; i++) {
        int m = mh * 128 + tm * 4 + i;
#pragma unroll
        for (int j = 0; j < 8; j++)
            KV[((long)bh * MM + m) * DHH + td * 8 + j] = acc[i][j];
    }
}

// ---------------- out = (Qf @ KV) / max(Qf@Ksum,1e-6) -> Att(B,L,D) --
__global__ void __launch_bounds__(256)
attn_out_kernel(const float* __restrict__ Qf, const float* __restrict__ KV,
                const float* __restrict__ Ksum, float* __restrict__ Att)
{
    int bh = blockIdx.x;
    int l0 = blockIdx.y * 32;
    int b = bh / HH, h = bh % HH;
    __shared__ float Qs[32][64];
    __shared__ float KVs[64][64];
    __shared__ float Ks[64];
    int tid = threadIdx.x;
    int lr = tid >> 3, dg = tid & 7;
    float acc[8];
#pragma unroll
    for (int j = 0; j < 8; j++) acc[j] = 0.f;
    float norm = 0.f;

    for (int mc = 0; mc < 4; mc++) {
        int m0 = mc * 64;
#pragma unroll
        for (int r = 0; r < 2; r++) {
            int idx = tid * 4 + r * 1024;
            int qr = idx >> 6, qm = idx & 63;
            *(float4*)&Qs[qr][qm] =
                *(const float4*)&Qf[((long)bh * LL + l0 + qr) * MM + m0 + qm];
        }
#pragma unroll
        for (int r = 0; r < 4; r++) {
            int idx = tid * 4 + r * 1024;
            int kr = idx >> 6, kd = idx & 63;
            *(float4*)&KVs[kr][kd] =
                *(const float4*)&KV[((long)bh * MM + m0 + kr) * DHH + kd];
        }
        if (tid < 64) Ks[tid] = Ksum[bh * MM + m0 + tid];
        __syncthreads();
#pragma unroll 8
        for (int mm = 0; mm < 64; mm++) {
            float qv = Qs[lr][mm];
            norm += qv * Ks[mm];
            float4 v0 = *(float4*)&KVs[mm][dg * 8];
            float4 v1 = *(float4*)&KVs[mm][dg * 8 + 4];
            acc[0] += qv * v0.x; acc[1] += qv * v0.y;
            acc[2] += qv * v0.z; acc[3] += qv * v0.w;
            acc[4] += qv * v1.x; acc[5] += qv * v1.y;
            acc[6] += qv * v1.z; acc[7] += qv * v1.w;
        }
        __syncthreads();
    }
    float inv = 1.0f / fmaxf(norm, 1e-6f);
    int l = l0 + lr;
    float* outp = Att + ((long)b * LL + l) * DD + h * 64 + dg * 8;
#pragma unroll
    for (int j = 0; j < 8; j++) outp[j] = acc[j] * inv;
}

// ---------------- pooling: score s = tanh(h@W1) @ W2 -----------------
__global__ void score_kernel(const float* __restrict__ Tt, const float* __restrict__ w2,
                             float* __restrict__ S)
{
    int row = blockIdx.x * 8 + (threadIdx.x >> 5);
    int lane = threadIdx.x & 31;
    const float* t = Tt + (long)row * HID;
    float s = 0.f;
    for (int i = lane; i < HID; i += 32) s += t[i] * w2[i];
#pragma unroll
    for (int o = 16; o > 0; o >>= 1) s += __shfl_xor_sync(0xffffffffu, s, o);
    if (lane == 0) S[row] = s;
}

__global__ void softmax_kernel(const float* __restrict__ S, float* __restrict__ Alpha) {
    int b = blockIdx.x, tid = threadIdx.x;  // 256 threads
    __shared__ float sh[8];
    float mx = -1e30f;
    for (int i = tid; i < LL; i += 256) mx = fmaxf(mx, S[b * LL + i]);
#pragma unroll
    for (int o = 16; o > 0; o >>= 1) mx = fmaxf(mx, __shfl_xor_sync(0xffffffffu, mx, o));
    if ((tid & 31) == 0) sh[tid >> 5] = mx;
    __syncthreads();
    if (tid == 0) { float t = sh[0]; for (int i = 1; i < 8; i++) t = fmaxf(t, sh[i]); sh[0] = t; }
    __syncthreads();
    float m = sh[0];
    __syncthreads();
    float sum = 0.f;
    for (int i = tid; i < LL; i += 256) sum += expf(S[b * LL + i] - m);
#pragma unroll
    for (int o = 16; o > 0; o >>= 1) sum += __shfl_xor_sync(0xffffffffu, sum, o);
    if ((tid & 31) == 0) sh[tid >> 5] = sum;
    __syncthreads();
    if (tid == 0) { float t = 0; for (int i = 0; i < 8; i++) t += sh[i]; sh[0] = t; }
    __syncthreads();
    float inv = 1.0f / sh[0];
    for (int i = tid; i < LL; i += 256) Alpha[b * LL + i] = expf(S[b * LL + i] - m) * inv;
}

__global__ void muvar_kernel(const float* __restrict__ Hx, const float* __restrict__ Alpha,
                             float* __restrict__ Feat)
{
    int b = blockIdx.x, d = threadIdx.x;  // 512 threads
    float mu = 0.f, sq = 0.f;
    for (int l = 0; l < LL; l++) {
        float a = Alpha[b * LL + l];
        float v = Hx[((long)b * LL + l) * DD + d];
        mu += a * v;
        sq += a * v * v;
    }
    Feat[b * 2 * DD + d] = mu;
    Feat[b * 2 * DD + DD + d] = sqrtf(fmaxf(sq - mu * mu, 1e-8f));
}

__global__ void head_kernel(const float* __restrict__ Feat, const float* __restrict__ Wh,
                            const float* __restrict__ bh_, float* __restrict__ Out)
{
    int b = blockIdx.x, tid = threadIdx.x;  // 256 threads
    float p[NC];
#pragma unroll
    for (int n = 0; n < NC; n++) p[n] = 0.f;
    for (int i = tid; i < 2 * DD; i += 256) {
        float f = Feat[b * 2 * DD + i];
        const float* w = Wh + (long)i * NC;
#pragma unroll
        for (int n = 0; n < NC; n++) p[n] += f * w[n];
    }
    __shared__ float red[NC][256];
#pragma unroll
    for (int n = 0; n < NC; n++) red[n][tid] = p[n];
    __syncthreads();
    for (int s = 128; s > 0; s >>= 1) {
        if (tid < s)
#pragma unroll
            for (int n = 0; n < NC; n++) red[n][tid] += red[n][tid + s];
        __syncthreads();
    }
    if (tid < NC) Out[b * NC + tid] = red[tid][0] + bh_[tid];
}

// ---------------- launch --------------------------------------------
extern "C" void kernel_launch(void* const* d_in, const int* in_sizes, int n_in,
                              void* d_out, int out_size)
{
    const float* x        = (const float*)d_in[0];
    const float* patch_W  = (const float*)d_in[1];
    const float* patch_b  = (const float*)d_in[2];
    const float* patch_g  = (const float*)d_in[3];
    const float* patch_be = (const float*)d_in[4];
    const float* ln1_g    = (const float*)d_in[5];
    const float* ln1_b    = (const float*)d_in[6];
    const float* qW       = (const float*)d_in[7];
    const float* kW       = (const float*)d_in[8];
    const float* vW       = (const float*)d_in[9];
    const float* oW       = (const float*)d_in[10];
    const float* ob       = (const float*)d_in[11];
    const float* omega    = (const float*)d_in[12];
    const float* ln2_g    = (const float*)d_in[13];
    const float* ln2_b    = (const float*)d_in[14];
    const float* f1W      = (const float*)d_in[15];
    const float* f1b      = (const float*)d_in[16];
    const float* f2W      = (const float*)d_in[17];
    const float* f2b      = (const float*)d_in[18];
    const float* poolW1   = (const float*)d_in[19];
    const float* poolW2   = (const float*)d_in[20];
    const float* headW    = (const float*)d_in[21];
    const float* headb    = (const float*)d_in[22];
    float* out = (float*)d_out;

    float* arena;
    cudaGetSymbolAddress((void**)&arena, g_arena);
    float* h    = arena + OFF_H;
    float* a    = arena + OFF_A;
    float* big  = arena + OFF_BIG;       // q,k,v live here; later ffn hidden
    float* q    = big;
    float* k    = big + SZ_H;
    float* v    = big + 2 * SZ_H;
    float* ffn  = big;                   // ROWS*FFND = 2*SZ_H <= SZ_BIG
    float* qf   = arena + OFF_QF;
    float* kf   = arena + OFF_KF;
    float* tok  = arena + OFF_ATT;       // tok and att share (disjoint live ranges)
    float* att  = arena + OFF_ATT;
    float* kv   = arena + OFF_KV;
    float* ksum = arena + OFF_KSUM;
    float* scr  = arena + OFF_SCR;
    float* alp  = arena + OFF_ALP;
    float* feat = arena + OFF_FEAT;

    dim3 g512(DD / 128, ROWS / 128);    // (4, 200)
    dim3 g1024(FFND / 128, ROWS / 128); // (8, 200)
    dim3 g128(HID / 128, ROWS / 128);   // (1, 200)

    // patchify + embed + LN
    patchify_kernel<<<ROWS, CP>>>(x, tok);
    gemm_kernel<0, false><<<g512, 256>>>(tok, patch_W, patch_b, a, ROWS, DD, CP);
    ln_kernel<<<ROWS, 256>>>(a, patch_g, patch_be, h);

    for (int l = 0; l < NLAYER; l++) {
        // attention
        ln_kernel<<<ROWS, 256>>>(h, ln1_g + l * DD, ln1_b + l * DD, a);
        gemm_kernel<0, false><<<g512, 256>>>(a, qW + (long)l * DD * DD, nullptr, q, ROWS, DD, DD);
        gemm_kernel<0, false><<<g512, 256>>>(a, kW + (long)l * DD * DD, nullptr, k, ROWS, DD, DD);
        gemm_kernel<0, false><<<g512, 256>>>(a, vW + (long)l * DD * DD, nullptr, v, ROWS, DD, DD);
        phi_kernel<<<2 * ROWS, 256>>>(q, k, omega + (long)l * DHH * MM, qf, kf);
        ksum_kernel<<<BB * HH, MM>>>(kf, ksum);
        kv_kernel<<<BB * HH * 2, 256>>>(kf, v, kv);
        attn_out_kernel<<<dim3(BB * HH, LL / 32), 256>>>(qf, kv, ksum, att);
        gemm_kernel<0, true><<<g512, 256>>>(att, oW + (long)l * DD * DD, ob + l * DD, h, ROWS, DD, DD);
        // FFN (ffn aliases q/k/v — q,k,v dead after attn_out)
        ln_kernel<<<ROWS, 256>>>(h, ln2_g + l * DD, ln2_b + l * DD, a);
        gemm_kernel<1, false><<<g1024, 256>>>(a, f1W + (long)l * DD * FFND, f1b + l * FFND, ffn, ROWS, FFND, DD);
        gemm_kernel<0, true><<<g512, 256>>>(ffn, f2W + (long)l * FFND * DD, f2b + l * DD, h, ROWS, DD, FFND);
    }

    // attentive statistics pooling + head
    gemm_kernel<2, false><<<g128, 256>>>(h, poolW1, nullptr, ffn, ROWS, HID, DD);
    score_kernel<<<ROWS / 8, 256>>>(ffn, poolW2, scr);
    softmax_kernel<<<BB, 256>>>(scr, alp);
    muvar_kernel<<<BB, DD>>>(h, alp, feat);
    head_kernel<<<BB, 256>>>(feat, headW, headb, out);
}

// round 4
// speedup vs baseline: 1.1079x; 1.1079x over previous
#include <cuda_runtime.h>
#include <math.h>
#include <stdint.h>

// ---------------- problem dims ----------------
#define BB   32
#define CC   8
#define TT   20000
#define PP   25
#define LL   800        // TT/PP
#define CP   200        // CC*PP
#define DD   512
#define HH   8
#define DHH  64
#define MM   256
#define NLAYER 2
#define FFND 1024
#define NC   10
#define HID  128
#define ROWS (BB*LL)    // 25600

// ---------------- scratch arena ----------------
#define SZ_H    (ROWS*DD)
#define SZ_BIG  (3*ROWS*DD)
#define SZ_PHI  (BB*HH*LL*MM)
#define OFF_H    0
#define OFF_A    (OFF_H   + SZ_H)
#define OFF_BIG  (OFF_A   + SZ_H)
#define OFF_QF   (OFF_BIG + SZ_BIG)
#define OFF_KF   (OFF_QF  + SZ_PHI)
#define OFF_ATT  (OFF_KF  + SZ_PHI)
#define OFF_KV   (OFF_ATT + SZ_H)
#define OFF_KSUM (OFF_KV  + BB*HH*MM*DHH)
#define OFF_SCR  (OFF_KSUM+ BB*HH*MM)
#define OFF_ALP  (OFF_SCR + ROWS)
#define OFF_FEAT (OFF_ALP + ROWS)
#define ARENA_SZ (OFF_FEAT + BB*2*DD)

__device__ float g_arena[ARENA_SZ];

// ---------------- patchify ----------------
__global__ void patchify_kernel(const float* __restrict__ x, float* __restrict__ tok) {
    int bl = blockIdx.x;
    int b = bl / LL, l = bl % LL;
    int t = threadIdx.x;              // 200 threads
    int c = t / PP, p = t % PP;
    tok[bl * CP + t] = x[(b * CC + c) * TT + l * PP + p];
}

// ---------------- TF32 helpers ----------------
__device__ __forceinline__ void split_tf32(float x, uint32_t& hi, uint32_t& lo) {
    uint32_t h;
    asm("cvt.rna.tf32.f32 %0, %1;" : "=r"(h) : "f"(x));
    float r = x - __uint_as_float(h);
    uint32_t l;
    asm("cvt.rna.tf32.f32 %0, %1;" : "=r"(l) : "f"(r));
    hi = h; lo = l;
}

__device__ __forceinline__ void mma_tf32(float* d, const uint32_t* a, const uint32_t* b) {
    asm volatile(
        "mma.sync.aligned.m16n8k8.row.col.f32.tf32.tf32.f32 "
        "{%0,%1,%2,%3}, {%4,%5,%6,%7}, {%8,%9}, {%0,%1,%2,%3};"
        : "+f"(d[0]), "+f"(d[1]), "+f"(d[2]), "+f"(d[3])
        : "r"(a[0]), "r"(a[1]), "r"(a[2]), "r"(a[3]), "r"(b[0]), "r"(b[1]));
}

// ---------------- 3xTF32 tensor-core GEMM -------------------------------
// C = act(A@W + bias) [+C].  A:(Mr x K) rm, W:(K x N) rm, C:(Mr x N) rm.
// Tiles: 128x128x16, 256 threads (8 warps as 2m x 4n, warp tile 64x32).
#define Bb_M 128
#define Bb_N 128
#define Bb_K 16
#define AS_STRIDE 20
#define BS_STRIDE 136

template<int ACT, bool RESID>
__global__ void __launch_bounds__(256)
gemm_tf32_kernel(const float* __restrict__ A, const float* __restrict__ W,
                 const float* __restrict__ bias, float* __restrict__ C,
                 int Mr, int N, int K)
{
    __shared__ float As[2][Bb_M][AS_STRIDE];
    __shared__ float Bs[2][Bb_K][BS_STRIDE];

    int tid = threadIdx.x;
    int lane = tid & 31, wid = tid >> 5;
    int wm = wid & 1, wn = wid >> 1;          // warp tile: m = wm*64, n = wn*32
    int m0 = blockIdx.y * Bb_M, n0 = blockIdx.x * Bb_N;

    float acc[4][4][4];
#pragma unroll
    for (int i = 0; i < 4; i++)
#pragma unroll
        for (int j = 0; j < 4; j++)
#pragma unroll
            for (int r = 0; r < 4; r++) acc[i][j][r] = 0.f;

    float4 aR[2], bR[2];
    int nK = (K + Bb_K - 1) / Bb_K;

    // -------- tile loaders --------
    auto load_tiles = [&](int k0) {
#pragma unroll
        for (int r = 0; r < 2; r++) {
            int i = tid + r * 256;                 // 0..511
            int row = i >> 2, c4 = (i & 3) * 4;
            int gk = k0 + c4;
            const float* p = A + (long)(m0 + row) * K + gk;
            float4 v = make_float4(0.f, 0.f, 0.f, 0.f);
            if (gk + 3 < K) v = *(const float4*)p;
            else {
                if (gk     < K) v.x = p[0];
                if (gk + 1 < K) v.y = p[1];
                if (gk + 2 < K) v.z = p[2];
            }
            aR[r] = v;
        }
#pragma unroll
        for (int r = 0; r < 2; r++) {
            int i = tid + r * 256;
            int row = i >> 5, c4 = (i & 31) * 4;
            int gk = k0 + row;
            float4 v = make_float4(0.f, 0.f, 0.f, 0.f);
            if (gk < K) v = *(const float4*)&W[(long)gk * N + n0 + c4];
            bR[r] = v;
        }
    };
    auto store_tiles = [&](int buf) {
#pragma unroll
        for (int r = 0; r < 2; r++) {
            int i = tid + r * 256;
            int row = i >> 2, c4 = (i & 3) * 4;
            *(float4*)&As[buf][row][c4] = aR[r];
        }
#pragma unroll
        for (int r = 0; r < 2; r++) {
            int i = tid + r * 256;
            int row = i >> 5, c4 = (i & 31) * 4;
            *(float4*)&Bs[buf][row][c4] = bR[r];
        }
    };

    load_tiles(0);
    store_tiles(0);
    __syncthreads();

    for (int kt = 0; kt < nK; kt++) {
        int buf = kt & 1;
        if (kt + 1 < nK) load_tiles((kt + 1) * Bb_K);

        // -------- compute from smem[buf] --------
#pragma unroll
        for (int ks = 0; ks < Bb_K; ks += 8) {
            uint32_t ahi[4][4], alo[4][4];
#pragma unroll
            for (int mt = 0; mt < 4; mt++) {
                int mrow = wm * 64 + mt * 16 + (lane >> 2);
                int kc = ks + (lane & 3);
                float a0 = As[buf][mrow][kc];
                float a1 = As[buf][mrow + 8][kc];
                float a2 = As[buf][mrow][kc + 4];
                float a3 = As[buf][mrow + 8][kc + 4];
                split_tf32(a0, ahi[mt][0], alo[mt][0]);
                split_tf32(a1, ahi[mt][1], alo[mt][1]);
                split_tf32(a2, ahi[mt][2], alo[mt][2]);
                split_tf32(a3, ahi[mt][3], alo[mt][3]);
            }
            uint32_t bhi[4][2], blo[4][2];
#pragma unroll
            for (int nt = 0; nt < 4; nt++) {
                int ncol = wn * 32 + nt * 8 + (lane >> 2);
                float b0 = Bs[buf][ks + (lane & 3)][ncol];
                float b1 = Bs[buf][ks + 4 + (lane & 3)][ncol];
                split_tf32(b0, bhi[nt][0], blo[nt][0]);
                split_tf32(b1, bhi[nt][1], blo[nt][1]);
            }
#pragma unroll
            for (int mt = 0; mt < 4; mt++)
#pragma unroll
                for (int nt = 0; nt < 4; nt++) {
                    mma_tf32(acc[mt][nt], ahi[mt], bhi[nt]);
                    mma_tf32(acc[mt][nt], alo[mt], bhi[nt]);
                    mma_tf32(acc[mt][nt], ahi[mt], blo[nt]);
                }
        }

        if (kt + 1 < nK) {
            store_tiles(buf ^ 1);
            __syncthreads();
        }
    }

    // -------- epilogue --------
#pragma unroll
    for (int mt = 0; mt < 4; mt++) {
#pragma unroll
        for (int nt = 0; nt < 4; nt++) {
            int row = m0 + wm * 64 + mt * 16 + (lane >> 2);
            int col = n0 + wn * 32 + nt * 8 + (lane & 3) * 2;
#pragma unroll
            for (int r = 0; r < 4; r++) {
                int rr = row + (r >> 1) * 8;
                int cc = col + (r & 1);
                float v = acc[mt][nt][r];
                if (bias) v += bias[cc];
                if (ACT == 1) v = 0.5f * v * (1.0f + erff(v * 0.70710678118654752f));
                if (ACT == 2) v = tanhf(v);
                float* cp = &C[(long)rr * N + cc];
                if (RESID) v += *cp;
                *cp = v;
            }
        }
    }
}

// ---------------- LayerNorm over D=512 -------------------------------
__global__ void ln_kernel(const float* __restrict__ X, const float* __restrict__ g,
                          const float* __restrict__ bta, float* __restrict__ Y)
{
    long row = blockIdx.x;
    int tid = threadIdx.x;  // 256
    __shared__ float sh[8];
    float v0 = X[row * DD + tid];
    float v1 = X[row * DD + tid + 256];
    float s = v0 + v1;
#pragma unroll
    for (int o = 16; o > 0; o >>= 1) s += __shfl_xor_sync(0xffffffffu, s, o);
    if ((tid & 31) == 0) sh[tid >> 5] = s;
    __syncthreads();
    if (tid == 0) { float t = 0; for (int i = 0; i < 8; i++) t += sh[i]; sh[0] = t; }
    __syncthreads();
    float mu = sh[0] * (1.0f / DD);
    __syncthreads();
    float d0 = v0 - mu, d1 = v1 - mu;
    s = d0 * d0 + d1 * d1;
#pragma unroll
    for (int o = 16; o > 0; o >>= 1) s += __shfl_xor_sync(0xffffffffu, s, o);
    if ((tid & 31) == 0) sh[tid >> 5] = s;
    __syncthreads();
    if (tid == 0) { float t = 0; for (int i = 0; i < 8; i++) t += sh[i]; sh[0] = t; }
    __syncthreads();
    float var = sh[0] * (1.0f / DD);
    float rstd = rsqrtf(var + 1e-5f);
    Y[row * DD + tid]       = d0 * rstd * g[tid]       + bta[tid];
    Y[row * DD + tid + 256] = d1 * rstd * g[tid + 256] + bta[tid + 256];
}

// ---------------- FAVOR+ phi: Q and K in one launch -------------------
__global__ void phi_kernel(const float* __restrict__ Q, const float* __restrict__ K,
                           const float* __restrict__ omega,
                           float* __restrict__ QPhi, float* __restrict__ KPhi)
{
    int bl = blockIdx.x;
    const float* X = (bl < ROWS) ? Q : K;
    float* Phi = (bl < ROWS) ? QPhi : KPhi;
    if (bl >= ROWS) bl -= ROWS;
    __shared__ float xs[DD];
    int tid = threadIdx.x;  // 256
    const float inv4 = 0.35355339059327379f;  // 1/64^0.25
    xs[tid]       = X[(long)bl * DD + tid]       * inv4;
    xs[tid + 256] = X[(long)bl * DD + tid + 256] * inv4;
    __syncthreads();
    int h = tid >> 5, lane = tid & 31;
    const float* xh = &xs[h * DHH];
    float nsq = 0.f;
#pragma unroll
    for (int d = 0; d < DHH; d++) nsq += xh[d] * xh[d];
    nsq *= 0.5f;
    float acc[8];
#pragma unroll
    for (int j = 0; j < 8; j++) acc[j] = 0.f;
    for (int d = 0; d < DHH; d++) {
        float xv = xh[d];
        const float* om = omega + d * MM + lane;
#pragma unroll
        for (int j = 0; j < 8; j++) acc[j] += xv * om[j * 32];
    }
    int b = bl / LL, l = bl % LL;
    float* outp = Phi + ((long)(b * HH + h) * LL + l) * MM + lane;
#pragma unroll
    for (int j = 0; j < 8; j++) outp[j * 32] = expf(acc[j] - nsq) * 0.0625f;
}

// ---------------- Ksum ----------------------------
__global__ void ksum_kernel(const float* __restrict__ Kf, float* __restrict__ Ksum) {
    int bh = blockIdx.x;
    int m = threadIdx.x;   // 256
    const float* p = Kf + (long)bh * LL * MM + m;
    float s = 0.f;
    for (int l = 0; l < LL; l++) s += p[l * MM];
    Ksum[bh * MM + m] = s;
}

// ---------------- KV[b,h,m,d] = sum_l Kf[l,m] V[l,d] ----------------
__global__ void __launch_bounds__(256)
kv_kernel(const float* __restrict__ Kf, const float* __restrict__ V,
          float* __restrict__ KV)
{
    int bh = blockIdx.x >> 1, mh = blockIdx.x & 1;
    int b = bh / HH, h = bh % HH;
    __shared__ float Ks[32][128];
    __shared__ float Vs[32][64];
    int tid = threadIdx.x;
    int tm = tid >> 3, td = tid & 7;
    float acc[4][8];
#pragma unroll
    for (int i = 0; i < 4; i++)
#pragma unroll
        for (int j = 0; j < 8; j++) acc[i][j] = 0.f;

    for (int l0 = 0; l0 < LL; l0 += 32) {
#pragma unroll
        for (int r = 0; r < 4; r++) {
            int idx = tid * 4 + r * 1024;
            int lr = idx >> 7, mc = idx & 127;
            *(float4*)&Ks[lr][mc] =
                *(const float4*)&Kf[((long)bh * LL + l0 + lr) * MM + mh * 128 + mc];
        }
#pragma unroll
        for (int r = 0; r < 2; r++) {
            int idx = tid * 4 + r * 1024;
            int lr = idx >> 6, dc = idx & 63;
            *(float4*)&Vs[lr][dc] =
                *(const float4*)&V[((long)b * LL + l0 + lr) * DD + h * 64 + dc];
        }
        __syncthreads();
#pragma unroll 4
        for (int l = 0; l < 32; l++) {
            float km[4];
#pragma unroll
            for (int i = 0; i < 4; i++) km[i] = Ks[l][tm * 4 + i];
            float4 v0 = *(float4*)&Vs[l][td * 8];
            float4 v1 = *(float4*)&Vs[l][td * 8 + 4];
            float vr[8] = {v0.x, v0.y, v0.z, v0.w, v1.x, v1.y, v1.z, v1.w};
#pragma unroll
            for (int i = 0; i < 4; i++)
#pragma unroll
                for (int j = 0; j < 8; j++) acc[i][j] += km[i] * vr[j];
        }
        __syncthreads();
    }
#pragma unroll
    for (int i = 0; i < 4; i++) {
        int m = mh * 128 + tm * 4 + i;
#pragma unroll
        for (int j = 0; j < 8; j++)
            KV[((long)bh * MM + m) * DHH + td * 8 + j] = acc[i][j];
    }
}

// ---------------- out = (Qf @ KV) / max(Qf@Ksum,1e-6) ----------------
__global__ void __launch_bounds__(256)
attn_out_kernel(const float* __restrict__ Qf, const float* __restrict__ KV,
                const float* __restrict__ Ksum, float* __restrict__ Att)
{
    int bh = blockIdx.x;
    int l0 = blockIdx.y * 32;
    int b = bh / HH, h = bh % HH;
    __shared__ float Qs[32][64];
    __shared__ float KVs[64][64];
    __shared__ float Ks[64];
    int tid = threadIdx.x;
    int lr = tid >> 3, dg = tid & 7;
    float acc[8];
#pragma unroll
    for (int j = 0; j < 8; j++) acc[j] = 0.f;
    float norm = 0.f;

    for (int mc = 0; mc < 4; mc++) {
        int m0 = mc * 64;
#pragma unroll
        for (int r = 0; r < 2; r++) {
            int idx = tid * 4 + r * 1024;
            int qr = idx >> 6, qm = idx & 63;
            *(float4*)&Qs[qr][qm] =
                *(const float4*)&Qf[((long)bh * LL + l0 + qr) * MM + m0 + qm];
        }
#pragma unroll
        for (int r = 0; r < 4; r++) {
            int idx = tid * 4 + r * 1024;
            int kr = idx >> 6, kd = idx & 63;
            *(float4*)&KVs[kr][kd] =
                *(const float4*)&KV[((long)bh * MM + m0 + kr) * DHH + kd];
        }
        if (tid < 64) Ks[tid] = Ksum[bh * MM + m0 + tid];
        __syncthreads();
#pragma unroll 8
        for (int mm = 0; mm < 64; mm++) {
            float qv = Qs[lr][mm];
            norm += qv * Ks[mm];
            float4 v0 = *(float4*)&KVs[mm][dg * 8];
            float4 v1 = *(float4*)&KVs[mm][dg * 8 + 4];
            acc[0] += qv * v0.x; acc[1] += qv * v0.y;
            acc[2] += qv * v0.z; acc[3] += qv * v0.w;
            acc[4] += qv * v1.x; acc[5] += qv * v1.y;
            acc[6] += qv * v1.z; acc[7] += qv * v1.w;
        }
        __syncthreads();
    }
    float inv = 1.0f / fmaxf(norm, 1e-6f);
    int l = l0 + lr;
    float* outp = Att + ((long)b * LL + l) * DD + h * 64 + dg * 8;
#pragma unroll
    for (int j = 0; j < 8; j++) outp[j] = acc[j] * inv;
}

// ---------------- pooling ---------------------------------------------
__global__ void score_kernel(const float* __restrict__ Tt, const float* __restrict__ w2,
                             float* __restrict__ S)
{
    int row = blockIdx.x * 8 + (threadIdx.x >> 5);
    int lane = threadIdx.x & 31;
    const float* t = Tt + (long)row * HID;
    float s = 0.f;
    for (int i = lane; i < HID; i += 32) s += t[i] * w2[i];
#pragma unroll
    for (int o = 16; o > 0; o >>= 1) s += __shfl_xor_sync(0xffffffffu, s, o);
    if (lane == 0) S[row] = s;
}

__global__ void softmax_kernel(const float* __restrict__ S, float* __restrict__ Alpha) {
    int b = blockIdx.x, tid = threadIdx.x;  // 256 threads
    __shared__ float sh[8];
    float mx = -1e30f;
    for (int i = tid; i < LL; i += 256) mx = fmaxf(mx, S[b * LL + i]);
#pragma unroll
    for (int o = 16; o > 0; o >>= 1) mx = fmaxf(mx, __shfl_xor_sync(0xffffffffu, mx, o));
    if ((tid & 31) == 0) sh[tid >> 5] = mx;
    __syncthreads();
    if (tid == 0) { float t = sh[0]; for (int i = 1; i < 8; i++) t = fmaxf(t, sh[i]); sh[0] = t; }
    __syncthreads();
    float m = sh[0];
    __syncthreads();
    float sum = 0.f;
    for (int i = tid; i < LL; i += 256) sum += expf(S[b * LL + i] - m);
#pragma unroll
    for (int o = 16; o > 0; o >>= 1) sum += __shfl_xor_sync(0xffffffffu, sum, o);
    if ((tid & 31) == 0) sh[tid >> 5] = sum;
    __syncthreads();
    if (tid == 0) { float t = 0; for (int i = 0; i < 8; i++) t += sh[i]; sh[0] = t; }
    __syncthreads();
    float inv = 1.0f / sh[0];
    for (int i = tid; i < LL; i += 256) Alpha[b * LL + i] = expf(S[b * LL + i] - m) * inv;
}

__global__ void muvar_kernel(const float* __restrict__ Hx, const float* __restrict__ Alpha,
                             float* __restrict__ Feat)
{
    int b = blockIdx.x, d = threadIdx.x;  // 512 threads
    float mu = 0.f, sq = 0.f;
    for (int l = 0; l < LL; l++) {
        float a = Alpha[b * LL + l];
        float v = Hx[((long)b * LL + l) * DD + d];
        mu += a * v;
        sq += a * v * v;
    }
    Feat[b * 2 * DD + d] = mu;
    Feat[b * 2 * DD + DD + d] = sqrtf(fmaxf(sq - mu * mu, 1e-8f));
}

__global__ void head_kernel(const float* __restrict__ Feat, const float* __restrict__ Wh,
                            const float* __restrict__ bh_, float* __restrict__ Out)
{
    int b = blockIdx.x, tid = threadIdx.x;  // 256 threads
    float p[NC];
#pragma unroll
    for (int n = 0; n < NC; n++) p[n] = 0.f;
    for (int i = tid; i < 2 * DD; i += 256) {
        float f = Feat[b * 2 * DD + i];
        const float* w = Wh + (long)i * NC;
#pragma unroll
        for (int n = 0; n < NC; n++) p[n] += f * w[n];
    }
    __shared__ float red[NC][256];
#pragma unroll
    for (int n = 0; n < NC; n++) red[n][tid] = p[n];
    __syncthreads();
    for (int s = 128; s > 0; s >>= 1) {
        if (tid < s)
#pragma unroll
            for (int n = 0; n < NC; n++) red[n][tid] += red[n][tid + s];
        __syncthreads();
    }
    if (tid < NC) Out[b * NC + tid] = red[tid][0] + bh_[tid];
}

// ---------------- launch --------------------------------------------
extern "C" void kernel_launch(void* const* d_in, const int* in_sizes, int n_in,
                              void* d_out, int out_size)
{
    const float* x        = (const float*)d_in[0];
    const float* patch_W  = (const float*)d_in[1];
    const float* patch_b  = (const float*)d_in[2];
    const float* patch_g  = (const float*)d_in[3];
    const float* patch_be = (const float*)d_in[4];
    const float* ln1_g    = (const float*)d_in[5];
    const float* ln1_b    = (const float*)d_in[6];
    const float* qW       = (const float*)d_in[7];
    const float* kW       = (const float*)d_in[8];
    const float* vW       = (const float*)d_in[9];
    const float* oW       = (const float*)d_in[10];
    const float* ob       = (const float*)d_in[11];
    const float* omega    = (const float*)d_in[12];
    const float* ln2_g    = (const float*)d_in[13];
    const float* ln2_b    = (const float*)d_in[14];
    const float* f1W      = (const float*)d_in[15];
    const float* f1b      = (const float*)d_in[16];
    const float* f2W      = (const float*)d_in[17];
    const float* f2b      = (const float*)d_in[18];
    const float* poolW1   = (const float*)d_in[19];
    const float* poolW2   = (const float*)d_in[20];
    const float* headW    = (const float*)d_in[21];
    const float* headb    = (const float*)d_in[22];
    float* out = (float*)d_out;

    float* arena;
    cudaGetSymbolAddress((void**)&arena, g_arena);
    float* h    = arena + OFF_H;
    float* a    = arena + OFF_A;
    float* big  = arena + OFF_BIG;
    float* q    = big;
    float* k    = big + SZ_H;
    float* v    = big + 2 * SZ_H;
    float* ffn  = big;
    float* qf   = arena + OFF_QF;
    float* kf   = arena + OFF_KF;
    float* tok  = arena + OFF_ATT;
    float* att  = arena + OFF_ATT;
    float* kv   = arena + OFF_KV;
    float* ksum = arena + OFF_KSUM;
    float* scr  = arena + OFF_SCR;
    float* alp  = arena + OFF_ALP;
    float* feat = arena + OFF_FEAT;

    dim3 g512(DD / 128, ROWS / 128);    // (4, 200)
    dim3 g1024(FFND / 128, ROWS / 128); // (8, 200)
    dim3 g128(HID / 128, ROWS / 128);   // (1, 200)

    // patchify + embed + LN
    patchify_kernel<<<ROWS, CP>>>(x, tok);
    gemm_tf32_kernel<0, false><<<g512, 256>>>(tok, patch_W, patch_b, a, ROWS, DD, CP);
    ln_kernel<<<ROWS, 256>>>(a, patch_g, patch_be, h);

    for (int l = 0; l < NLAYER; l++) {
        // attention
        ln_kernel<<<ROWS, 256>>>(h, ln1_g + l * DD, ln1_b + l * DD, a);
        gemm_tf32_kernel<0, false><<<g512, 256>>>(a, qW + (long)l * DD * DD, nullptr, q, ROWS, DD, DD);
        gemm_tf32_kernel<0, false><<<g512, 256>>>(a, kW + (long)l * DD * DD, nullptr, k, ROWS, DD, DD);
        gemm_tf32_kernel<0, false><<<g512, 256>>>(a, vW + (long)l * DD * DD, nullptr, v, ROWS, DD, DD);
        phi_kernel<<<2 * ROWS, 256>>>(q, k, omega + (long)l * DHH * MM, qf, kf);
        ksum_kernel<<<BB * HH, MM>>>(kf, ksum);
        kv_kernel<<<BB * HH * 2, 256>>>(kf, v, kv);
        attn_out_kernel<<<dim3(BB * HH, LL / 32), 256>>>(qf, kv, ksum, att);
        gemm_tf32_kernel<0, true><<<g512, 256>>>(att, oW + (long)l * DD * DD, ob + l * DD, h, ROWS, DD, DD);
        // FFN
        ln_kernel<<<ROWS, 256>>>(h, ln2_g + l * DD, ln2_b + l * DD, a);
        gemm_tf32_kernel<1, false><<<g1024, 256>>>(a, f1W + (long)l * DD * FFND, f1b + l * FFND, ffn, ROWS, FFND, DD);
        gemm_tf32_kernel<0, true><<<g512, 256>>>(ffn, f2W + (long)l * FFND * DD, f2b + l * DD, h, ROWS, DD, FFND);
    }

    // attentive statistics pooling + head
    gemm_tf32_kernel<2, false><<<g128, 256>>>(h, poolW1, nullptr, ffn, ROWS, HID, DD);
    score_kernel<<<ROWS / 8, 256>>>(ffn, poolW2, scr);
    softmax_kernel<<<BB, 256>>>(scr, alp);
    muvar_kernel<<<BB, DD>>>(h, alp, feat);
    head_kernel<<<BB, 256>>>(feat, headW, headb, out);
}

// round 6
// speedup vs baseline: 1.1315x; 1.0213x over previous
#include <cuda_runtime.h>
#include <math.h>
#include <stdint.h>

// ---------------- problem dims ----------------
#define BB   32
#define CC   8
#define TT   20000
#define PP   25
#define LL   800        // TT/PP
#define CP   200        // CC*PP
#define DD   512
#define HH   8
#define DHH  64
#define MM   256
#define NLAYER 2
#define FFND 1024
#define NC   10
#define HID  128
#define ROWS (BB*LL)    // 25600

// ---------------- scratch arena ----------------
#define SZ_H    (ROWS*DD)
#define SZ_BIG  (3*ROWS*DD)
#define SZ_PHI  (BB*HH*LL*MM)
#define OFF_H    0
#define OFF_A    (OFF_H   + SZ_H)
#define OFF_BIG  (OFF_A   + SZ_H)
#define OFF_QF   (OFF_BIG + SZ_BIG)
#define OFF_KF   (OFF_QF  + SZ_PHI)
#define OFF_ATT  (OFF_KF  + SZ_PHI)
#define OFF_KV   (OFF_ATT + SZ_H)
#define OFF_KSUM (OFF_KV  + BB*HH*MM*DHH)
#define OFF_SCR  (OFF_KSUM+ BB*HH*MM)
#define OFF_ALP  (OFF_SCR + ROWS)
#define OFF_FEAT (OFF_ALP + ROWS)
#define ARENA_SZ (OFF_FEAT + BB*2*DD)

__device__ float g_arena[ARENA_SZ];

// ---------------- patchify ----------------
__global__ void patchify_kernel(const float* __restrict__ x, float* __restrict__ tok) {
    int bl = blockIdx.x;
    int b = bl / LL, l = bl % LL;
    int t = threadIdx.x;              // 200 threads
    int c = t / PP, p = t % PP;
    tok[bl * CP + t] = x[(b * CC + c) * TT + l * PP + p];
}

// ---------------- TF32 helpers ----------------
__device__ __forceinline__ void split_tf32(float x, uint32_t& hi, uint32_t& lo) {
    uint32_t h;
    asm("cvt.rna.tf32.f32 %0, %1;" : "=r"(h) : "f"(x));
    float r = x - __uint_as_float(h);
    uint32_t l;
    asm("cvt.rna.tf32.f32 %0, %1;" : "=r"(l) : "f"(r));
    hi = h; lo = l;
}

__device__ __forceinline__ void mma_tf32(float* d, const uint32_t* a, const uint32_t* b) {
    asm volatile(
        "mma.sync.aligned.m16n8k8.row.col.f32.tf32.tf32.f32 "
        "{%0,%1,%2,%3}, {%4,%5,%6,%7}, {%8,%9}, {%0,%1,%2,%3};"
        : "+f"(d[0]), "+f"(d[1]), "+f"(d[2]), "+f"(d[3])
        : "r"(a[0]), "r"(a[1]), "r"(a[2]), "r"(a[3]), "r"(b[0]), "r"(b[1]));
}

// ---------------- 3xTF32 tensor-core GEMM, pre-split smem ---------------
// C = act(A@W + bias) [+C].  A:(Mr x K) rm, W:(K x N) rm, C:(Mr x N) rm.
// Tiles: 128x128x16, 256 threads (8 warps as 2m x 4n, warp tile 64x32).
// smem holds hi/lo tf32 components (split once at store time), double-buffered.
#define Bb_M 128
#define Bb_N 128
#define Bb_K 16
#define AS_STRIDE 20
#define BS_STRIDE 136
#define A_TILE (Bb_M * AS_STRIDE)      // 2560 u32
#define B_TILE (Bb_K * BS_STRIDE)      // 2176 u32
#define SMEM_U32 (4 * A_TILE + 4 * B_TILE)   // 18944 u32 = 75776 B

template<int ACT, bool RESID>
__global__ void __launch_bounds__(256)
gemm_tf32_kernel(const float* __restrict__ A, const float* __restrict__ W,
                 const float* __restrict__ bias, float* __restrict__ C,
                 int Mr, int N, int K)
{
    extern __shared__ uint32_t sm[];
    uint32_t* AHp = sm;
    uint32_t* ALp = sm + 2 * A_TILE;
    uint32_t* BHp = sm + 4 * A_TILE;
    uint32_t* BLp = sm + 4 * A_TILE + 2 * B_TILE;

    int tid = threadIdx.x;
    int lane = tid & 31, wid = tid >> 5;
    int wm = wid & 1, wn = wid >> 1;          // warp tile: m = wm*64, n = wn*32
    int m0 = blockIdx.y * Bb_M, n0 = blockIdx.x * Bb_N;

    float acc[4][4][4];
#pragma unroll
    for (int i = 0; i < 4; i++)
#pragma unroll
        for (int j = 0; j < 4; j++)
#pragma unroll
            for (int r = 0; r < 4; r++) acc[i][j][r] = 0.f;

    float4 aR[2], bR[2];
    int nK = (K + Bb_K - 1) / Bb_K;

    // -------- tile loaders (gmem -> regs) --------
    auto load_tiles = [&](int k0) {
#pragma unroll
        for (int r = 0; r < 2; r++) {
            int i = tid + r * 256;                 // 0..511
            int row = i >> 2, c4 = (i & 3) * 4;
            int gk = k0 + c4;
            const float* p = A + (long)(m0 + row) * K + gk;
            float4 v = make_float4(0.f, 0.f, 0.f, 0.f);
            if (gk + 3 < K) v = *(const float4*)p;
            else {
                if (gk     < K) v.x = p[0];
                if (gk + 1 < K) v.y = p[1];
                if (gk + 2 < K) v.z = p[2];
            }
            aR[r] = v;
        }
#pragma unroll
        for (int r = 0; r < 2; r++) {
            int i = tid + r * 256;
            int row = i >> 5, c4 = (i & 31) * 4;
            int gk = k0 + row;
            float4 v = make_float4(0.f, 0.f, 0.f, 0.f);
            if (gk < K) v = *(const float4*)&W[(long)gk * N + n0 + c4];
            bR[r] = v;
        }
    };
    // -------- split + store (regs -> smem hi/lo) --------
    auto store_tiles = [&](int buf) {
        uint32_t* AH = AHp + buf * A_TILE;
        uint32_t* AL = ALp + buf * A_TILE;
        uint32_t* BH = BHp + buf * B_TILE;
        uint32_t* BL = BLp + buf * B_TILE;
#pragma unroll
        for (int r = 0; r < 2; r++) {
            int i = tid + r * 256;
            int row = i >> 2, c4 = (i & 3) * 4;
            float v4[4] = {aR[r].x, aR[r].y, aR[r].z, aR[r].w};
#pragma unroll
            for (int j = 0; j < 4; j++) {
                uint32_t hi, lo;
                split_tf32(v4[j], hi, lo);
                AH[row * AS_STRIDE + c4 + j] = hi;
                AL[row * AS_STRIDE + c4 + j] = lo;
            }
        }
#pragma unroll
        for (int r = 0; r < 2; r++) {
            int i = tid + r * 256;
            int row = i >> 5, c4 = (i & 31) * 4;
            float v4[4] = {bR[r].x, bR[r].y, bR[r].z, bR[r].w};
#pragma unroll
            for (int j = 0; j < 4; j++) {
                uint32_t hi, lo;
                split_tf32(v4[j], hi, lo);
                BH[row * BS_STRIDE + c4 + j] = hi;
                BL[row * BS_STRIDE + c4 + j] = lo;
            }
        }
    };

    load_tiles(0);
    store_tiles(0);
    __syncthreads();

    for (int kt = 0; kt < nK; kt++) {
        int buf = kt & 1;
        if (kt + 1 < nK) load_tiles((kt + 1) * Bb_K);

        const uint32_t* AH = AHp + buf * A_TILE;
        const uint32_t* AL = ALp + buf * A_TILE;
        const uint32_t* BH = BHp + buf * B_TILE;
        const uint32_t* BL = BLp + buf * B_TILE;

        // -------- compute from smem[buf]: pure LDS + MMA --------
#pragma unroll
        for (int ks = 0; ks < Bb_K; ks += 8) {
            uint32_t ahi[4][4], alo[4][4];
#pragma unroll
            for (int mt = 0; mt < 4; mt++) {
                int mrow = wm * 64 + mt * 16 + (lane >> 2);
                int kc = ks + (lane & 3);
                ahi[mt][0] = AH[mrow * AS_STRIDE + kc];
                ahi[mt][1] = AH[(mrow + 8) * AS_STRIDE + kc];
                ahi[mt][2] = AH[mrow * AS_STRIDE + kc + 4];
                ahi[mt][3] = AH[(mrow + 8) * AS_STRIDE + kc + 4];
                alo[mt][0] = AL[mrow * AS_STRIDE + kc];
                alo[mt][1] = AL[(mrow + 8) * AS_STRIDE + kc];
                alo[mt][2] = AL[mrow * AS_STRIDE + kc + 4];
                alo[mt][3] = AL[(mrow + 8) * AS_STRIDE + kc + 4];
            }
            uint32_t bhi[4][2], blo[4][2];
#pragma unroll
            for (int nt = 0; nt < 4; nt++) {
                int ncol = wn * 32 + nt * 8 + (lane >> 2);
                bhi[nt][0] = BH[(ks + (lane & 3)) * BS_STRIDE + ncol];
                bhi[nt][1] = BH[(ks + 4 + (lane & 3)) * BS_STRIDE + ncol];
                blo[nt][0] = BL[(ks + (lane & 3)) * BS_STRIDE + ncol];
                blo[nt][1] = BL[(ks + 4 + (lane & 3)) * BS_STRIDE + ncol];
            }
#pragma unroll
            for (int mt = 0; mt < 4; mt++)
#pragma unroll
                for (int nt = 0; nt < 4; nt++) {
                    mma_tf32(acc[mt][nt], ahi[mt], bhi[nt]);
                    mma_tf32(acc[mt][nt], alo[mt], bhi[nt]);
                    mma_tf32(acc[mt][nt], ahi[mt], blo[nt]);
                }
        }

        if (kt + 1 < nK) {
            store_tiles(buf ^ 1);
            __syncthreads();
        }
    }

    // -------- epilogue --------
#pragma unroll
    for (int mt = 0; mt < 4; mt++) {
#pragma unroll
        for (int nt = 0; nt < 4; nt++) {
            int row = m0 + wm * 64 + mt * 16 + (lane >> 2);
            int col = n0 + wn * 32 + nt * 8 + (lane & 3) * 2;
#pragma unroll
            for (int r = 0; r < 4; r++) {
                int rr = row + (r >> 1) * 8;
                int cc = col + (r & 1);
                float v = acc[mt][nt][r];
                if (bias) v += bias[cc];
                if (ACT == 1) v = 0.5f * v * (1.0f + erff(v * 0.70710678118654752f));
                if (ACT == 2) v = tanhf(v);
                float* cp = &C[(long)rr * N + cc];
                if (RESID) v += *cp;
                *cp = v;
            }
        }
    }
}

// ---------------- LayerNorm over D=512 -------------------------------
__global__ void ln_kernel(const float* __restrict__ X, const float* __restrict__ g,
                          const float* __restrict__ bta, float* __restrict__ Y)
{
    long row = blockIdx.x;
    int tid = threadIdx.x;  // 256
    __shared__ float sh[8];
    float v0 = X[row * DD + tid];
    float v1 = X[row * DD + tid + 256];
    float s = v0 + v1;
#pragma unroll
    for (int o = 16; o > 0; o >>= 1) s += __shfl_xor_sync(0xffffffffu, s, o);
    if ((tid & 31) == 0) sh[tid >> 5] = s;
    __syncthreads();
    if (tid == 0) { float t = 0; for (int i = 0; i < 8; i++) t += sh[i]; sh[0] = t; }
    __syncthreads();
    float mu = sh[0] * (1.0f / DD);
    __syncthreads();
    float d0 = v0 - mu, d1 = v1 - mu;
    s = d0 * d0 + d1 * d1;
#pragma unroll
    for (int o = 16; o > 0; o >>= 1) s += __shfl_xor_sync(0xffffffffu, s, o);
    if ((tid & 31) == 0) sh[tid >> 5] = s;
    __syncthreads();
    if (tid == 0) { float t = 0; for (int i = 0; i < 8; i++) t += sh[i]; sh[0] = t; }
    __syncthreads();
    float var = sh[0] * (1.0f / DD);
    float rstd = rsqrtf(var + 1e-5f);
    Y[row * DD + tid]       = d0 * rstd * g[tid]       + bta[tid];
    Y[row * DD + tid + 256] = d1 * rstd * g[tid + 256] + bta[tid + 256];
}

// ---------------- FAVOR+ phi: Q and K in one launch -------------------
__global__ void phi_kernel(const float* __restrict__ Q, const float* __restrict__ K,
                           const float* __restrict__ omega,
                           float* __restrict__ QPhi, float* __restrict__ KPhi)
{
    int bl = blockIdx.x;
    const float* X = (bl < ROWS) ? Q : K;
    float* Phi = (bl < ROWS) ? QPhi : KPhi;
    if (bl >= ROWS) bl -= ROWS;
    __shared__ float xs[DD];
    int tid = threadIdx.x;  // 256
    const float inv4 = 0.35355339059327379f;  // 1/64^0.25
    xs[tid]       = X[(long)bl * DD + tid]       * inv4;
    xs[tid + 256] = X[(long)bl * DD + tid + 256] * inv4;
    __syncthreads();
    int h = tid >> 5, lane = tid & 31;
    const float* xh = &xs[h * DHH];
    float nsq = 0.f;
#pragma unroll
    for (int d = 0; d < DHH; d++) nsq += xh[d] * xh[d];
    nsq *= 0.5f;
    float acc[8];
#pragma unroll
    for (int j = 0; j < 8; j++) acc[j] = 0.f;
    for (int d = 0; d < DHH; d++) {
        float xv = xh[d];
        const float* om = omega + d * MM + lane;
#pragma unroll
        for (int j = 0; j < 8; j++) acc[j] += xv * om[j * 32];
    }
    int b = bl / LL, l = bl % LL;
    float* outp = Phi + ((long)(b * HH + h) * LL + l) * MM + lane;
#pragma unroll
    for (int j = 0; j < 8; j++) outp[j * 32] = expf(acc[j] - nsq) * 0.0625f;
}

// ---------------- Ksum ----------------------------
__global__ void ksum_kernel(const float* __restrict__ Kf, float* __restrict__ Ksum) {
    int bh = blockIdx.x;
    int m = threadIdx.x;   // 256
    const float* p = Kf + (long)bh * LL * MM + m;
    float s = 0.f;
    for (int l = 0; l < LL; l++) s += p[l * MM];
    Ksum[bh * MM + m] = s;
}

// ---------------- KV[b,h,m,d] = sum_l Kf[l,m] V[l,d] ----------------
__global__ void __launch_bounds__(256)
kv_kernel(const float* __restrict__ Kf, const float* __restrict__ V,
          float* __restrict__ KV)
{
    int bh = blockIdx.x >> 1, mh = blockIdx.x & 1;
    int b = bh / HH, h = bh % HH;
    __shared__ float Ks[32][128];
    __shared__ float Vs[32][64];
    int tid = threadIdx.x;
    int tm = tid >> 3, td = tid & 7;
    float acc[4][8];
#pragma unroll
    for (int i = 0; i < 4; i++)
#pragma unroll
        for (int j = 0; j < 8; j++) acc[i][j] = 0.f;

    for (int l0 = 0; l0 < LL; l0 += 32) {
#pragma unroll
        for (int r = 0; r < 4; r++) {
            int idx = tid * 4 + r * 1024;
            int lr = idx >> 7, mc = idx & 127;
            *(float4*)&Ks[lr][mc] =
                *(const float4*)&Kf[((long)bh * LL + l0 + lr) * MM + mh * 128 + mc];
        }
#pragma unroll
        for (int r = 0; r < 2; r++) {
            int idx = tid * 4 + r * 1024;
            int lr = idx >> 6, dc = idx & 63;
            *(float4*)&Vs[lr][dc] =
                *(const float4*)&V[((long)b * LL + l0 + lr) * DD + h * 64 + dc];
        }
        __syncthreads();
#pragma unroll 4
        for (int l = 0; l < 32; l++) {
            float km[4];
#pragma unroll
            for (int i = 0; i < 4; i++) km[i] = Ks[l][tm * 4 + i];
            float4 v0 = *(float4*)&Vs[l][td * 8];
            float4 v1 = *(float4*)&Vs[l][td * 8 + 4];
            float vr[8] = {v0.x, v0.y, v0.z, v0.w, v1.x, v1.y, v1.z, v1.w};
#pragma unroll
            for (int i = 0; i < 4; i++)
#pragma unroll
                for (int j = 0; j < 8; j++) acc[i][j] += km[i] * vr[j];
        }
        __syncthreads();
    }
#pragma unroll
    for (int i = 0; i < 4; i++) {
        int m = mh * 128 + tm * 4 + i;
#pragma unroll
        for (int j = 0; j < 8; j++)
            KV[((long)bh * MM + m) * DHH + td * 8 + j] = acc[i][j];
    }
}

// ---------------- out = (Qf @ KV) / max(Qf@Ksum,1e-6) ----------------
__global__ void __launch_bounds__(256)
attn_out_kernel(const float* __restrict__ Qf, const float* __restrict__ KV,
                const float* __restrict__ Ksum, float* __restrict__ Att)
{
    int bh = blockIdx.x;
    int l0 = blockIdx.y * 32;
    int b = bh / HH, h = bh % HH;
    __shared__ float Qs[32][64];
    __shared__ float KVs[64][64];
    __shared__ float Ks[64];
    int tid = threadIdx.x;
    int lr = tid >> 3, dg = tid & 7;
    float acc[8];
#pragma unroll
    for (int j = 0; j < 8; j++) acc[j] = 0.f;
    float norm = 0.f;

    for (int mc = 0; mc < 4; mc++) {
        int m0 = mc * 64;
#pragma unroll
        for (int r = 0; r < 2; r++) {
            int idx = tid * 4 + r * 1024;
            int qr = idx >> 6, qm = idx & 63;
            *(float4*)&Qs[qr][qm] =
                *(const float4*)&Qf[((long)bh * LL + l0 + qr) * MM + m0 + qm];
        }
#pragma unroll
        for (int r = 0; r < 4; r++) {
            int idx = tid * 4 + r * 1024;
            int kr = idx >> 6, kd = idx & 63;
            *(float4*)&KVs[kr][kd] =
                *(const float4*)&KV[((long)bh * MM + m0 + kr) * DHH + kd];
        }
        if (tid < 64) Ks[tid] = Ksum[bh * MM + m0 + tid];
        __syncthreads();
#pragma unroll 8
        for (int mm = 0; mm < 64; mm++) {
            float qv = Qs[lr][mm];
            norm += qv * Ks[mm];
            float4 v0 = *(float4*)&KVs[mm][dg * 8];
            float4 v1 = *(float4*)&KVs[mm][dg * 8 + 4];
            acc[0] += qv * v0.x; acc[1] += qv * v0.y;
            acc[2] += qv * v0.z; acc[3] += qv * v0.w;
            acc[4] += qv * v1.x; acc[5] += qv * v1.y;
            acc[6] += qv * v1.z; acc[7] += qv * v1.w;
        }
        __syncthreads();
    }
    float inv = 1.0f / fmaxf(norm, 1e-6f);
    int l = l0 + lr;
    float* outp = Att + ((long)b * LL + l) * DD + h * 64 + dg * 8;
#pragma unroll
    for (int j = 0; j < 8; j++) outp[j] = acc[j] * inv;
}

// ---------------- pooling ---------------------------------------------
__global__ void score_kernel(const float* __restrict__ Tt, const float* __restrict__ w2,
                             float* __restrict__ S)
{
    int row = blockIdx.x * 8 + (threadIdx.x >> 5);
    int lane = threadIdx.x & 31;
    const float* t = Tt + (long)row * HID;
    float s = 0.f;
    for (int i = lane; i < HID; i += 32) s += t[i] * w2[i];
#pragma unroll
    for (int o = 16; o > 0; o >>= 1) s += __shfl_xor_sync(0xffffffffu, s, o);
    if (lane == 0) S[row] = s;
}

__global__ void softmax_kernel(const float* __restrict__ S, float* __restrict__ Alpha) {
    int b = blockIdx.x, tid = threadIdx.x;  // 256 threads
    __shared__ float sh[8];
    float mx = -1e30f;
    for (int i = tid; i < LL; i += 256) mx = fmaxf(mx, S[b * LL + i]);
#pragma unroll
    for (int o = 16; o > 0; o >>= 1) mx = fmaxf(mx, __shfl_xor_sync(0xffffffffu, mx, o));
    if ((tid & 31) == 0) sh[tid >> 5] = mx;
    __syncthreads();
    if (tid == 0) { float t = sh[0]; for (int i = 1; i < 8; i++) t = fmaxf(t, sh[i]); sh[0] = t; }
    __syncthreads();
    float m = sh[0];
    __syncthreads();
    float sum = 0.f;
    for (int i = tid; i < LL; i += 256) sum += expf(S[b * LL + i] - m);
#pragma unroll
    for (int o = 16; o > 0; o >>= 1) sum += __shfl_xor_sync(0xffffffffu, sum, o);
    if ((tid & 31) == 0) sh[tid >> 5] = sum;
    __syncthreads();
    if (tid == 0) { float t = 0; for (int i = 0; i < 8; i++) t += sh[i]; sh[0] = t; }
    __syncthreads();
    float inv = 1.0f / sh[0];
    for (int i = tid; i < LL; i += 256) Alpha[b * LL + i] = expf(S[b * LL + i] - m) * inv;
}

__global__ void muvar_kernel(const float* __restrict__ Hx, const float* __restrict__ Alpha,
                             float* __restrict__ Feat)
{
    int b = blockIdx.x, d = threadIdx.x;  // 512 threads
    float mu = 0.f, sq = 0.f;
    for (int l = 0; l < LL; l++) {
        float a = Alpha[b * LL + l];
        float v = Hx[((long)b * LL + l) * DD + d];
        mu += a * v;
        sq += a * v * v;
    }
    Feat[b * 2 * DD + d] = mu;
    Feat[b * 2 * DD + DD + d] = sqrtf(fmaxf(sq - mu * mu, 1e-8f));
}

__global__ void head_kernel(const float* __restrict__ Feat, const float* __restrict__ Wh,
                            const float* __restrict__ bh_, float* __restrict__ Out)
{
    int b = blockIdx.x, tid = threadIdx.x;  // 256 threads
    float p[NC];
#pragma unroll
    for (int n = 0; n < NC; n++) p[n] = 0.f;
    for (int i = tid; i < 2 * DD; i += 256) {
        float f = Feat[b * 2 * DD + i];
        const float* w = Wh + (long)i * NC;
#pragma unroll
        for (int n = 0; n < NC; n++) p[n] += f * w[n];
    }
    __shared__ float red[NC][256];
#pragma unroll
    for (int n = 0; n < NC; n++) red[n][tid] = p[n];
    __syncthreads();
    for (int s = 128; s > 0; s >>= 1) {
        if (tid < s)
#pragma unroll
            for (int n = 0; n < NC; n++) red[n][tid] += red[n][tid + s];
        __syncthreads();
    }
    if (tid < NC) Out[b * NC + tid] = red[tid][0] + bh_[tid];
}

// ---------------- launch --------------------------------------------
#define GEMM_SMEM (SMEM_U32 * 4)

extern "C" void kernel_launch(void* const* d_in, const int* in_sizes, int n_in,
                              void* d_out, int out_size)
{
    const float* x        = (const float*)d_in[0];
    const float* patch_W  = (const float*)d_in[1];
    const float* patch_b  = (const float*)d_in[2];
    const float* patch_g  = (const float*)d_in[3];
    const float* patch_be = (const float*)d_in[4];
    const float* ln1_g    = (const float*)d_in[5];
    const float* ln1_b    = (const float*)d_in[6];
    const float* qW       = (const float*)d_in[7];
    const float* kW       = (const float*)d_in[8];
    const float* vW       = (const float*)d_in[9];
    const float* oW       = (const float*)d_in[10];
    const float* ob       = (const float*)d_in[11];
    const float* omega    = (const float*)d_in[12];
    const float* ln2_g    = (const float*)d_in[13];
    const float* ln2_b    = (const float*)d_in[14];
    const float* f1W      = (const float*)d_in[15];
    const float* f1b      = (const float*)d_in[16];
    const float* f2W      = (const float*)d_in[17];
    const float* f2b      = (const float*)d_in[18];
    const float* poolW1   = (const float*)d_in[19];
    const float* poolW2   = (const float*)d_in[20];
    const float* headW    = (const float*)d_in[21];
    const float* headb    = (const float*)d_in[22];
    float* out = (float*)d_out;

    // opt-in to >48KB dynamic smem (idempotent, not stream-ordered)
    cudaFuncSetAttribute(gemm_tf32_kernel<0, false>, cudaFuncAttributeMaxDynamicSharedMemorySize, GEMM_SMEM);
    cudaFuncSetAttribute(gemm_tf32_kernel<0, true >, cudaFuncAttributeMaxDynamicSharedMemorySize, GEMM_SMEM);
    cudaFuncSetAttribute(gemm_tf32_kernel<1, false>, cudaFuncAttributeMaxDynamicSharedMemorySize, GEMM_SMEM);
    cudaFuncSetAttribute(gemm_tf32_kernel<2, false>, cudaFuncAttributeMaxDynamicSharedMemorySize, GEMM_SMEM);

    float* arena;
    cudaGetSymbolAddress((void**)&arena, g_arena);
    float* h    = arena + OFF_H;
    float* a    = arena + OFF_A;
    float* big  = arena + OFF_BIG;
    float* q    = big;
    float* k    = big + SZ_H;
    float* v    = big + 2 * SZ_H;
    float* ffn  = big;
    float* qf   = arena + OFF_QF;
    float* kf   = arena + OFF_KF;
    float* tok  = arena + OFF_ATT;
    float* att  = arena + OFF_ATT;
    float* kv   = arena + OFF_KV;
    float* ksum = arena + OFF_KSUM;
    float* scr  = arena + OFF_SCR;
    float* alp  = arena + OFF_ALP;
    float* feat = arena + OFF_FEAT;

    dim3 g512(DD / 128, ROWS / 128);    // (4, 200)
    dim3 g1024(FFND / 128, ROWS / 128); // (8, 200)
    dim3 g128(HID / 128, ROWS / 128);   // (1, 200)

    // patchify + embed + LN
    patchify_kernel<<<ROWS, CP>>>(x, tok);
    gemm_tf32_kernel<0, false><<<g512, 256, GEMM_SMEM>>>(tok, patch_W, patch_b, a, ROWS, DD, CP);
    ln_kernel<<<ROWS, 256>>>(a, patch_g, patch_be, h);

    for (int l = 0; l < NLAYER; l++) {
        // attention
        ln_kernel<<<ROWS, 256>>>(h, ln1_g + l * DD, ln1_b + l * DD, a);
        gemm_tf32_kernel<0, false><<<g512, 256, GEMM_SMEM>>>(a, qW + (long)l * DD * DD, nullptr, q, ROWS, DD, DD);
        gemm_tf32_kernel<0, false><<<g512, 256, GEMM_SMEM>>>(a, kW + (long)l * DD * DD, nullptr, k, ROWS, DD, DD);
        gemm_tf32_kernel<0, false><<<g512, 256, GEMM_SMEM>>>(a, vW + (long)l * DD * DD, nullptr, v, ROWS, DD, DD);
        phi_kernel<<<2 * ROWS, 256>>>(q, k, omega + (long)l * DHH * MM, qf, kf);
        ksum_kernel<<<BB * HH, MM>>>(kf, ksum);
        kv_kernel<<<BB * HH * 2, 256>>>(kf, v, kv);
        attn_out_kernel<<<dim3(BB * HH, LL / 32), 256>>>(qf, kv, ksum, att);
        gemm_tf32_kernel<0, true><<<g512, 256, GEMM_SMEM>>>(att, oW + (long)l * DD * DD, ob + l * DD, h, ROWS, DD, DD);
        // FFN
        ln_kernel<<<ROWS, 256>>>(h, ln2_g + l * DD, ln2_b + l * DD, a);
        gemm_tf32_kernel<1, false><<<g1024, 256, GEMM_SMEM>>>(a, f1W + (long)l * DD * FFND, f1b + l * FFND, ffn, ROWS, FFND, DD);
        gemm_tf32_kernel<0, true><<<g512, 256, GEMM_SMEM>>>(ffn, f2W + (long)l * FFND * DD, f2b + l * DD, h, ROWS, DD, FFND);
    }

    // attentive statistics pooling + head
    gemm_tf32_kernel<2, false><<<g128, 256, GEMM_SMEM>>>(h, poolW1, nullptr, ffn, ROWS, HID, DD);
    score_kernel<<<ROWS / 8, 256>>>(ffn, poolW2, scr);
    softmax_kernel<<<BB, 256>>>(scr, alp);
    muvar_kernel<<<BB, DD>>>(h, alp, feat);
    head_kernel<<<BB, 256>>>(feat, headW, headb, out);
}